// round 14
// baseline (speedup 1.0000x reference)
#include <cuda_runtime.h>
#include <cuda_bf16.h>
#include <math.h>
#include <stdint.h>

#define IN_DIM  2048
#define HID     1024
#define ATT_NUM 40
#define BATCH   4096

#define BM 128
#define BN 128
#define KC 64               // K chunk: 64 k-rows (A rows 128B, B rows 256B)
#define NC (IN_DIM / KC)    // 32
#define NSTG 3
#define NTILES (HID / BN)   // 8

// dynamic smem layout (per CTA)
#define OFF_B1S  0
#define OFF_W2S  1024
#define OFF_RED  2048
#define OFF_TILES 4096
#define STAGE_BYTES 32768                // A 16KB ([128][128B] SW128) + B 16KB ([64][256B])
#define A_OFF(s) (OFF_TILES + (s) * STAGE_BYTES)
#define B_OFF(s) (A_OFF(s) + 16384)
#define SMEM_TOTAL (OFF_TILES + NSTG * STAGE_BYTES)   // 102400 -> 2 CTAs/SM

// static device scratch
__device__ __nv_bfloat16 g_xb[(size_t)BATCH * IN_DIM];             // 16 MB [b][k]
__device__ __nv_bfloat16 g_w1b[(size_t)ATT_NUM * IN_DIM * HID];    // 168 MB [a][k][n] native
__device__ float g_ypart[(size_t)BATCH * ATT_NUM * NTILES];

__device__ __forceinline__ uint32_t smem_u32(const void* p) {
    uint32_t a;
    asm("{ .reg .u64 t; cvta.to.shared.u64 t, %1; cvt.u32.u64 %0, t; }" : "=r"(a) : "l"(p));
    return a;
}
__device__ __forceinline__ void cp16(uint32_t dst, const void* src) {
    asm volatile("cp.async.cg.shared.global [%0], [%1], 16;" :: "r"(dst), "l"(src));
}
#define CP_COMMIT() asm volatile("cp.async.commit_group;" ::: "memory")
#define CP_WAIT(n)  asm volatile("cp.async.wait_group %0;" :: "n"(n) : "memory")

__device__ __forceinline__ void ldsm4(uint32_t* r, uint32_t addr) {
    asm volatile("ldmatrix.sync.aligned.m8n8.x4.shared.b16 {%0,%1,%2,%3}, [%4];"
                 : "=r"(r[0]), "=r"(r[1]), "=r"(r[2]), "=r"(r[3]) : "r"(addr));
}
__device__ __forceinline__ void ldsm4t(uint32_t* r, uint32_t addr) {
    asm volatile("ldmatrix.sync.aligned.m8n8.x4.trans.shared.b16 {%0,%1,%2,%3}, [%4];"
                 : "=r"(r[0]), "=r"(r[1]), "=r"(r[2]), "=r"(r[3]) : "r"(addr));
}
__device__ __forceinline__ void mma16816(float* c, const uint32_t* a, uint32_t b0, uint32_t b1) {
    asm volatile(
        "mma.sync.aligned.m16n8k16.row.col.f32.bf16.bf16.f32 "
        "{%0,%1,%2,%3}, {%4,%5,%6,%7}, {%8,%9}, {%0,%1,%2,%3};\n"
        : "+f"(c[0]), "+f"(c[1]), "+f"(c[2]), "+f"(c[3])
        : "r"(a[0]), "r"(a[1]), "r"(a[2]), "r"(a[3]), "r"(b0), "r"(b1));
}

// ===== prepass: streaming fp32 -> bf16 (x and W1 in one launch) =====
#define X_F4 (BATCH * IN_DIM / 4)                         // 2,097,152 float4s
#define W1_F4 ((size_t)ATT_NUM * IN_DIM * HID / 4)        // 20,971,520 float4s
__global__ void convert_all_kernel(const float* __restrict__ x, const float* __restrict__ W1) {
    size_t i = (size_t)blockIdx.x * blockDim.x + threadIdx.x;
    float4 v;
    uint2* dst;
    if (i < X_F4) {
        v = reinterpret_cast<const float4*>(x)[i];
        dst = reinterpret_cast<uint2*>(g_xb) + i;
    } else {
        size_t j = i - X_F4;
        v = reinterpret_cast<const float4*>(W1)[j];
        dst = reinterpret_cast<uint2*>(g_w1b) + j;
    }
    __nv_bfloat162 lo = __floats2bfloat162_rn(v.x, v.y);
    __nv_bfloat162 hi = __floats2bfloat162_rn(v.z, v.w);
    uint2 u;
    u.x = *reinterpret_cast<uint32_t*>(&lo);
    u.y = *reinterpret_cast<uint32_t*>(&hi);
    *dst = u;
}

// ===== fused GEMM + bias + gelu + W2-dot =====
extern __shared__ __align__(1024) char dynsmem[];

// One quarter of a chunk's loads: A 1 cp16/thread + B 1 cp16/thread.
__device__ __forceinline__ void load_part(uint32_t smem_base, int kc, int s, int part,
                                          const __nv_bfloat16* xA, const __nv_bfloat16* wB,
                                          int tid) {
    uint32_t ab = smem_base + A_OFF(s);
    uint32_t bb = smem_base + B_OFF(s);
    const __nv_bfloat16* xk = xA + kc * KC;
    const __nv_bfloat16* wk = wB + (size_t)(kc * KC) * HID;   // [k][n], n contiguous
    int o = tid + part * 256;                                 // 0..1023
    {
        int row = o >> 3, j = o & 7;                          // A: 128 rows x 8 x 16B
        uint32_t bo = (uint32_t)((row << 7) | (j << 4));
        uint32_t sw = bo ^ ((bo >> 3) & 0x70);
        cp16(ab + sw, xk + (size_t)row * IN_DIM + j * 8);
    }
    {
        int krow = o >> 4, c = o & 15;                        // B: 64 rows x 16 x 16B
        uint32_t sw = (uint32_t)(krow * 256) + (uint32_t)((c ^ (krow & 7)) << 4);
        cp16(bb + sw, wk + (size_t)krow * HID + c * 8);
    }
}

__global__ __launch_bounds__(256, 2)
void fused_head_gemm(const float* __restrict__ b1, const float* __restrict__ W2) {
    uint32_t smem_base = smem_u32(dynsmem);
    const int tid  = threadIdx.x;
    const int wid  = tid >> 5;
    const int lane = tid & 31;
    const int warp_m = wid & 1;     // 2 warps in M (64 rows each)
    const int warp_n = wid >> 1;    // 4 warps in N (32 cols each)
    const int g = lane >> 2;
    const int t = lane & 3;

    const int m0 = blockIdx.x * BM;
    const int n0 = blockIdx.y * BN;
    const int a  = blockIdx.z;

    const __nv_bfloat16* xA = g_xb  + (size_t)m0 * IN_DIM;
    const __nv_bfloat16* wB = g_w1b + (size_t)a * IN_DIM * HID + n0;

    if (tid < BN) {   // bias / W2 tile to smem
        float* b1s = (float*)(dynsmem + OFF_B1S);
        float* w2s = (float*)(dynsmem + OFF_W2S);
        b1s[tid] = b1[a * HID + n0 + tid];
        w2s[tid] = W2[a * HID + n0 + tid];
    }

    // ---- lane constants for fragment loads ----
    const int arow = lane & 15;
    const int ahi  = lane >> 4;
    const int asw  = arow & 7;
    const int krow_l = (((lane >> 3) & 1) << 3) + (lane & 7);
    const int nc_l   = lane >> 4;
    const int bxor   = krow_l & 7;

    uint32_t a_rowbase[4];
    #pragma unroll
    for (int fm = 0; fm < 4; fm++)
        a_rowbase[fm] = (uint32_t)((warp_m * 64 + fm * 16 + arow) << 7);
    uint32_t b_coloff[2];
    #pragma unroll
    for (int p = 0; p < 2; p++)
        b_coloff[p] = (uint32_t)((((warp_n * 4 + p * 2 + nc_l) ^ bxor)) << 4);

    float acc[4][4][4];
    #pragma unroll
    for (int fm = 0; fm < 4; fm++)
        #pragma unroll
        for (int fn = 0; fn < 4; fn++)
            #pragma unroll
            for (int r = 0; r < 4; r++) acc[fm][fn][r] = 0.0f;

    // prologue: stages 0..NSTG-2
    #pragma unroll
    for (int s = 0; s < NSTG - 1; s++) {
        #pragma unroll
        for (int part = 0; part < 4; part++) load_part(smem_base, s, s, part, xA, wB, tid);
        CP_COMMIT();
    }

    uint32_t Af[4][4];      // single-buffered A fragments (issued well ahead of first consumer)
    uint32_t Bf[2][2][4];   // double-buffered B fragments

    for (int kc = 0; kc < NC; ++kc) {
        if (kc == NC - 1) { CP_WAIT(0); } else { CP_WAIT(1); }
        __syncthreads();
        const uint32_t abase = smem_base + A_OFF(kc % NSTG);
        const uint32_t bbase = smem_base + B_OFF(kc % NSTG);
        const int pf = (kc + NSTG - 1 < NC);
        const int pfs = (kc + NSTG - 1) % NSTG;

        // B fragments for ks=0
        #pragma unroll
        for (int p = 0; p < 2; p++)
            ldsm4t(Bf[0][p], bbase + (uint32_t)(krow_l * 256) + b_coloff[p]);

        #pragma unroll
        for (int ks = 0; ks < 4; ks++) {
            const int cur = ks & 1, nxt = cur ^ 1;
            // A fragments for this ks (first in issue order -> max slack before mma)
            #pragma unroll
            for (int fm = 0; fm < 4; fm++)
                ldsm4(Af[fm], abase + a_rowbase[fm] + (((ks * 2 + ahi) ^ asw) << 4));
            // B fragments for next ks (a full ks of slack)
            if (ks < 3) {
                #pragma unroll
                for (int p = 0; p < 2; p++)
                    ldsm4t(Bf[nxt][p], bbase + (uint32_t)(((ks + 1) * 16 + krow_l) * 256) + b_coloff[p]);
            }
            if (pf) load_part(smem_base, kc + NSTG - 1, pfs, ks, xA, wB, tid);
            #pragma unroll
            for (int fm = 0; fm < 4; fm++)
                #pragma unroll
                for (int p = 0; p < 2; p++) {
                    mma16816(acc[fm][2 * p],     Af[fm], Bf[cur][p][0], Bf[cur][p][1]);
                    mma16816(acc[fm][2 * p + 1], Af[fm], Bf[cur][p][2], Bf[cur][p][3]);
                }
        }
        if (pf) CP_COMMIT();
    }

    // ---- epilogue ----
    const float* b1s = (const float*)(dynsmem + OFF_B1S);
    const float* w2s = (const float*)(dynsmem + OFF_W2S);
    float* red = (float*)(dynsmem + OFF_RED);   // [128][4]

    float pr[8];
    #pragma unroll
    for (int i = 0; i < 8; i++) pr[i] = 0.0f;

    #pragma unroll
    for (int fm = 0; fm < 4; fm++) {
        #pragma unroll
        for (int fn = 0; fn < 4; fn++) {
            int cbase = warp_n * 32 + fn * 8 + 2 * t;
            #pragma unroll
            for (int cc = 0; cc < 2; cc++) {
                int col = cbase + cc;
                float bb = b1s[col];
                float w2 = w2s[col];
                float v0 = acc[fm][fn][cc]     + bb;
                float v1 = acc[fm][fn][cc + 2] + bb;
                float h0 = 0.5f * v0 * (1.0f + erff(v0 * 0.70710678118654752f));
                float h1 = 0.5f * v1 * (1.0f + erff(v1 * 0.70710678118654752f));
                pr[fm * 2 + 0] += h0 * w2;
                pr[fm * 2 + 1] += h1 * w2;
            }
        }
    }
    #pragma unroll
    for (int i = 0; i < 8; i++) {
        pr[i] += __shfl_xor_sync(0xffffffffu, pr[i], 1);
        pr[i] += __shfl_xor_sync(0xffffffffu, pr[i], 2);
    }
    __syncthreads();
    if (t == 0) {
        #pragma unroll
        for (int i = 0; i < 8; i++) {
            int row = warp_m * 64 + (i >> 1) * 16 + (i & 1) * 8 + g;
            red[row * 4 + warp_n] = pr[i];
        }
    }
    __syncthreads();
    if (tid < BM) {
        float sum = red[tid * 4 + 0] + red[tid * 4 + 1] + red[tid * 4 + 2] + red[tid * 4 + 3];
        g_ypart[((size_t)(m0 + tid) * ATT_NUM + a) * NTILES + blockIdx.y] = sum;
    }
}

__global__ void finalize_kernel(const float* __restrict__ b2, float* __restrict__ out) {
    int i = blockIdx.x * blockDim.x + threadIdx.x;
    if (i >= BATCH * ATT_NUM) return;
    int a = i % ATT_NUM;
    float s = 0.0f;
    #pragma unroll
    for (int j = 0; j < NTILES; j++) s += g_ypart[(size_t)i * NTILES + j];
    s += b2[a];
    out[i] = 1.0f / (1.0f + expf(-s));
}

extern "C" void kernel_launch(void* const* d_in, const int* in_sizes, int n_in,
                              void* d_out, int out_size) {
    const float* x  = (const float*)d_in[0];
    const float* W1 = (const float*)d_in[1];
    const float* b1 = (const float*)d_in[2];
    const float* W2 = (const float*)d_in[3];
    const float* b2 = (const float*)d_in[4];
    float* out = (float*)d_out;

    cudaFuncSetAttribute(fused_head_gemm, cudaFuncAttributeMaxDynamicSharedMemorySize, SMEM_TOTAL);

    {
        size_t total_f4 = (size_t)X_F4 + W1_F4;   // 23,068,672
        convert_all_kernel<<<(unsigned)(total_f4 / 256), 256>>>(x, W1);
    }

    dim3 grid(BATCH / BM, HID / BN, ATT_NUM);   // (32, 8, 40); x fastest -> W1 strip reuse in-wave
    fused_head_gemm<<<grid, 256, SMEM_TOTAL>>>(b1, W2);

    int n = BATCH * ATT_NUM;
    finalize_kernel<<<(n + 255) / 256, 256>>>(b2, out);
}

// round 15
// speedup vs baseline: 1.6105x; 1.6105x over previous
#include <cuda_runtime.h>
#include <cuda_bf16.h>
#include <math.h>
#include <stdint.h>

#define IN_DIM  2048
#define HID     1024
#define ATT_NUM 40
#define BATCH   4096

#define BM 128
#define BN 128
#define KC 64               // K chunk: 64 k-rows (A rows 128B, B rows 256B)
#define NC (IN_DIM / KC)    // 32
#define NSTG 3
#define NTILES (HID / BN)   // 8

// dynamic smem layout (per CTA)
#define OFF_B1S  0
#define OFF_W2S  1024
#define OFF_RED  2048
#define OFF_TILES 4096
#define STAGE_BYTES 32768                // A 16KB ([128][128B] SW128) + B 16KB ([64][256B])
#define A_OFF(s) (OFF_TILES + (s) * STAGE_BYTES)
#define B_OFF(s) (A_OFF(s) + 16384)
#define SMEM_TOTAL (OFF_TILES + NSTG * STAGE_BYTES)   // 102400 -> 2 CTAs/SM

// static device scratch
__device__ __nv_bfloat16 g_xb[(size_t)BATCH * IN_DIM];             // 16 MB [b][k]
__device__ __nv_bfloat16 g_w1b[(size_t)ATT_NUM * IN_DIM * HID];    // 168 MB [a][k][n] native
__device__ float g_ypart[(size_t)BATCH * ATT_NUM * NTILES];

__device__ __forceinline__ uint32_t smem_u32(const void* p) {
    uint32_t a;
    asm("{ .reg .u64 t; cvta.to.shared.u64 t, %1; cvt.u32.u64 %0, t; }" : "=r"(a) : "l"(p));
    return a;
}
__device__ __forceinline__ void cp16(uint32_t dst, const void* src) {
    asm volatile("cp.async.cg.shared.global [%0], [%1], 16;" :: "r"(dst), "l"(src));
}
#define CP_COMMIT() asm volatile("cp.async.commit_group;" ::: "memory")
#define CP_WAIT(n)  asm volatile("cp.async.wait_group %0;" :: "n"(n) : "memory")

__device__ __forceinline__ void ldsm4(uint32_t* r, uint32_t addr) {
    asm volatile("ldmatrix.sync.aligned.m8n8.x4.shared.b16 {%0,%1,%2,%3}, [%4];"
                 : "=r"(r[0]), "=r"(r[1]), "=r"(r[2]), "=r"(r[3]) : "r"(addr));
}
__device__ __forceinline__ void ldsm4t(uint32_t* r, uint32_t addr) {
    asm volatile("ldmatrix.sync.aligned.m8n8.x4.trans.shared.b16 {%0,%1,%2,%3}, [%4];"
                 : "=r"(r[0]), "=r"(r[1]), "=r"(r[2]), "=r"(r[3]) : "r"(addr));
}
__device__ __forceinline__ void mma16816(float* c, const uint32_t* a, uint32_t b0, uint32_t b1) {
    asm volatile(
        "mma.sync.aligned.m16n8k16.row.col.f32.bf16.bf16.f32 "
        "{%0,%1,%2,%3}, {%4,%5,%6,%7}, {%8,%9}, {%0,%1,%2,%3};\n"
        : "+f"(c[0]), "+f"(c[1]), "+f"(c[2]), "+f"(c[3])
        : "r"(a[0]), "r"(a[1]), "r"(a[2]), "r"(a[3]), "r"(b0), "r"(b1));
}

// ===== prepass: streaming fp32 -> bf16 (x and W1 in one launch) =====
#define X_F4 (BATCH * IN_DIM / 4)                         // 2,097,152 float4s
#define W1_F4 ((size_t)ATT_NUM * IN_DIM * HID / 4)        // 20,971,520 float4s
__global__ void convert_all_kernel(const float* __restrict__ x, const float* __restrict__ W1) {
    size_t i = (size_t)blockIdx.x * blockDim.x + threadIdx.x;
    float4 v;
    uint2* dst;
    if (i < X_F4) {
        v = reinterpret_cast<const float4*>(x)[i];
        dst = reinterpret_cast<uint2*>(g_xb) + i;
    } else {
        size_t j = i - X_F4;
        v = reinterpret_cast<const float4*>(W1)[j];
        dst = reinterpret_cast<uint2*>(g_w1b) + j;
    }
    __nv_bfloat162 lo = __floats2bfloat162_rn(v.x, v.y);
    __nv_bfloat162 hi = __floats2bfloat162_rn(v.z, v.w);
    uint2 u;
    u.x = *reinterpret_cast<uint32_t*>(&lo);
    u.y = *reinterpret_cast<uint32_t*>(&hi);
    *dst = u;
}

// ===== fused GEMM + bias + gelu + W2-dot =====
extern __shared__ __align__(1024) char dynsmem[];

// One quarter of a chunk's loads: A 1 cp16/thread + B 1 cp16/thread.
__device__ __forceinline__ void load_part(uint32_t smem_base, int kc, int s, int part,
                                          const __nv_bfloat16* xA, const __nv_bfloat16* wB,
                                          int tid) {
    uint32_t ab = smem_base + A_OFF(s);
    uint32_t bb = smem_base + B_OFF(s);
    const __nv_bfloat16* xk = xA + kc * KC;
    const __nv_bfloat16* wk = wB + (size_t)(kc * KC) * HID;   // [k][n], n contiguous
    int o = tid + part * 256;                                 // 0..1023
    {
        int row = o >> 3, j = o & 7;                          // A: 128 rows x 8 x 16B
        uint32_t bo = (uint32_t)((row << 7) | (j << 4));
        uint32_t sw = bo ^ ((bo >> 3) & 0x70);
        cp16(ab + sw, xk + (size_t)row * IN_DIM + j * 8);
    }
    {
        int krow = o >> 4, c = o & 15;                        // B: 64 rows x 16 x 16B
        uint32_t sw = (uint32_t)(krow * 256) + (uint32_t)((c ^ (krow & 7)) << 4);
        cp16(bb + sw, wk + (size_t)krow * HID + c * 8);
    }
}

__global__ __launch_bounds__(256, 2)
void fused_head_gemm(const float* __restrict__ b1, const float* __restrict__ W2) {
    uint32_t smem_base = smem_u32(dynsmem);
    const int tid  = threadIdx.x;
    const int wid  = tid >> 5;
    const int lane = tid & 31;
    const int warp_m = wid & 1;     // 2 warps in M (64 rows each)
    const int warp_n = wid >> 1;    // 4 warps in N (32 cols each)
    const int g = lane >> 2;
    const int t = lane & 3;

    const int m0 = blockIdx.x * BM;
    const int n0 = blockIdx.y * BN;
    const int a  = blockIdx.z;

    const __nv_bfloat16* xA = g_xb  + (size_t)m0 * IN_DIM;
    const __nv_bfloat16* wB = g_w1b + (size_t)a * IN_DIM * HID + n0;

    if (tid < BN) {   // bias / W2 tile to smem
        float* b1s = (float*)(dynsmem + OFF_B1S);
        float* w2s = (float*)(dynsmem + OFF_W2S);
        b1s[tid] = b1[a * HID + n0 + tid];
        w2s[tid] = W2[a * HID + n0 + tid];
    }

    // ---- lane constants for fragment loads ----
    const int arow = lane & 15;
    const int ahi  = lane >> 4;
    const int asw  = arow & 7;
    const int krow_l = (((lane >> 3) & 1) << 3) + (lane & 7);
    const int nc_l   = lane >> 4;
    const int bxor   = krow_l & 7;

    uint32_t a_rowbase[4];
    #pragma unroll
    for (int fm = 0; fm < 4; fm++)
        a_rowbase[fm] = (uint32_t)((warp_m * 64 + fm * 16 + arow) << 7);
    uint32_t b_coloff[2];
    #pragma unroll
    for (int p = 0; p < 2; p++)
        b_coloff[p] = (uint32_t)((((warp_n * 4 + p * 2 + nc_l) ^ bxor)) << 4);

    float acc[4][4][4];
    #pragma unroll
    for (int fm = 0; fm < 4; fm++)
        #pragma unroll
        for (int fn = 0; fn < 4; fn++)
            #pragma unroll
            for (int r = 0; r < 4; r++) acc[fm][fn][r] = 0.0f;

    // prologue: stages 0..NSTG-2
    #pragma unroll
    for (int s = 0; s < NSTG - 1; s++) {
        #pragma unroll
        for (int part = 0; part < 4; part++) load_part(smem_base, s, s, part, xA, wB, tid);
        CP_COMMIT();
    }

    uint32_t Af[4][4], Bf[2][4];   // single-buffered; cross-CTA interleave hides latency

    for (int kc = 0; kc < NC; ++kc) {
        if (kc == NC - 1) { CP_WAIT(0); } else { CP_WAIT(1); }
        __syncthreads();
        const uint32_t abase = smem_base + A_OFF(kc % NSTG);
        const uint32_t bbase = smem_base + B_OFF(kc % NSTG);
        const int pf = (kc + NSTG - 1 < NC);
        const int pfs = (kc + NSTG - 1) % NSTG;

        #pragma unroll
        for (int ks = 0; ks < 4; ks++) {
            #pragma unroll
            for (int p = 0; p < 2; p++)
                ldsm4t(Bf[p], bbase + (uint32_t)((ks * 16 + krow_l) * 256) + b_coloff[p]);
            #pragma unroll
            for (int fm = 0; fm < 4; fm++)
                ldsm4(Af[fm], abase + a_rowbase[fm] + (((ks * 2 + ahi) ^ asw) << 4));
            if (pf) load_part(smem_base, kc + NSTG - 1, pfs, ks, xA, wB, tid);
            #pragma unroll
            for (int fm = 0; fm < 4; fm++)
                #pragma unroll
                for (int p = 0; p < 2; p++) {
                    mma16816(acc[fm][2 * p],     Af[fm], Bf[p][0], Bf[p][1]);
                    mma16816(acc[fm][2 * p + 1], Af[fm], Bf[p][2], Bf[p][3]);
                }
        }
        if (pf) CP_COMMIT();
    }

    // ---- epilogue ----
    const float* b1s = (const float*)(dynsmem + OFF_B1S);
    const float* w2s = (const float*)(dynsmem + OFF_W2S);
    float* red = (float*)(dynsmem + OFF_RED);   // [128][4]

    float pr[8];
    #pragma unroll
    for (int i = 0; i < 8; i++) pr[i] = 0.0f;

    #pragma unroll
    for (int fm = 0; fm < 4; fm++) {
        #pragma unroll
        for (int fn = 0; fn < 4; fn++) {
            int cbase = warp_n * 32 + fn * 8 + 2 * t;
            #pragma unroll
            for (int cc = 0; cc < 2; cc++) {
                int col = cbase + cc;
                float bb = b1s[col];
                float w2 = w2s[col];
                float v0 = acc[fm][fn][cc]     + bb;
                float v1 = acc[fm][fn][cc + 2] + bb;
                float h0 = 0.5f * v0 * (1.0f + erff(v0 * 0.70710678118654752f));
                float h1 = 0.5f * v1 * (1.0f + erff(v1 * 0.70710678118654752f));
                pr[fm * 2 + 0] += h0 * w2;
                pr[fm * 2 + 1] += h1 * w2;
            }
        }
    }
    #pragma unroll
    for (int i = 0; i < 8; i++) {
        pr[i] += __shfl_xor_sync(0xffffffffu, pr[i], 1);
        pr[i] += __shfl_xor_sync(0xffffffffu, pr[i], 2);
    }
    __syncthreads();
    if (t == 0) {
        #pragma unroll
        for (int i = 0; i < 8; i++) {
            int row = warp_m * 64 + (i >> 1) * 16 + (i & 1) * 8 + g;
            red[row * 4 + warp_n] = pr[i];
        }
    }
    __syncthreads();
    if (tid < BM) {
        float sum = red[tid * 4 + 0] + red[tid * 4 + 1] + red[tid * 4 + 2] + red[tid * 4 + 3];
        g_ypart[((size_t)(m0 + tid) * ATT_NUM + a) * NTILES + blockIdx.y] = sum;
    }
}

__global__ void finalize_kernel(const float* __restrict__ b2, float* __restrict__ out) {
    int i = blockIdx.x * blockDim.x + threadIdx.x;
    if (i >= BATCH * ATT_NUM) return;
    int a = i % ATT_NUM;
    float s = 0.0f;
    #pragma unroll
    for (int j = 0; j < NTILES; j++) s += g_ypart[(size_t)i * NTILES + j];
    s += b2[a];
    out[i] = 1.0f / (1.0f + expf(-s));
}

extern "C" void kernel_launch(void* const* d_in, const int* in_sizes, int n_in,
                              void* d_out, int out_size) {
    const float* x  = (const float*)d_in[0];
    const float* W1 = (const float*)d_in[1];
    const float* b1 = (const float*)d_in[2];
    const float* W2 = (const float*)d_in[3];
    const float* b2 = (const float*)d_in[4];
    float* out = (float*)d_out;

    cudaFuncSetAttribute(fused_head_gemm, cudaFuncAttributeMaxDynamicSharedMemorySize, SMEM_TOTAL);

    {
        size_t total_f4 = (size_t)X_F4 + W1_F4;   // 23,068,672
        convert_all_kernel<<<(unsigned)(total_f4 / 256), 256>>>(x, W1);
    }

    dim3 grid(BATCH / BM, HID / BN, ATT_NUM);   // (32, 8, 40); x fastest -> W1 strip reuse in-wave
    fused_head_gemm<<<grid, 256, SMEM_TOTAL>>>(b1, W2);

    int n = BATCH * ATT_NUM;
    finalize_kernel<<<(n + 255) / 256, 256>>>(b2, out);
}

// round 16
// speedup vs baseline: 1.6213x; 1.0067x over previous
#include <cuda_runtime.h>
#include <cuda_bf16.h>
#include <math.h>
#include <stdint.h>

#define IN_DIM  2048
#define HID     1024
#define ATT_NUM 40
#define BATCH   4096

#define BM 128
#define BN 128
#define KC 64               // K chunk: 64 k-rows (A rows 128B, B rows 256B)
#define NC (IN_DIM / KC)    // 32
#define NSTG 3
#define NTILES (HID / BN)   // 8

// dynamic smem layout (per CTA)
#define OFF_B1S  0
#define OFF_W2S  1024
#define OFF_RED  2048
#define OFF_TILES 4096
#define STAGE_BYTES 32768                // A 16KB ([128][128B] SW128) + B 16KB ([64][256B])
#define A_OFF(s) (OFF_TILES + (s) * STAGE_BYTES)
#define B_OFF(s) (A_OFF(s) + 16384)
#define SMEM_TOTAL (OFF_TILES + NSTG * STAGE_BYTES)   // 102400 -> 2 CTAs/SM

// static device scratch
__device__ __nv_bfloat16 g_xb[(size_t)BATCH * IN_DIM];             // 16 MB [b][k]
__device__ __nv_bfloat16 g_w1b[(size_t)ATT_NUM * IN_DIM * HID];    // 168 MB [a][k][n] native
__device__ float g_ypart[(size_t)BATCH * ATT_NUM * NTILES];

__device__ __forceinline__ uint32_t smem_u32(const void* p) {
    uint32_t a;
    asm("{ .reg .u64 t; cvta.to.shared.u64 t, %1; cvt.u32.u64 %0, t; }" : "=r"(a) : "l"(p));
    return a;
}
__device__ __forceinline__ void cp16(uint32_t dst, const void* src) {
    asm volatile("cp.async.cg.shared.global [%0], [%1], 16;" :: "r"(dst), "l"(src));
}
#define CP_COMMIT() asm volatile("cp.async.commit_group;" ::: "memory")
#define CP_WAIT(n)  asm volatile("cp.async.wait_group %0;" :: "n"(n) : "memory")

__device__ __forceinline__ void ldsm4(uint32_t* r, uint32_t addr) {
    asm volatile("ldmatrix.sync.aligned.m8n8.x4.shared.b16 {%0,%1,%2,%3}, [%4];"
                 : "=r"(r[0]), "=r"(r[1]), "=r"(r[2]), "=r"(r[3]) : "r"(addr));
}
__device__ __forceinline__ void ldsm4t(uint32_t* r, uint32_t addr) {
    asm volatile("ldmatrix.sync.aligned.m8n8.x4.trans.shared.b16 {%0,%1,%2,%3}, [%4];"
                 : "=r"(r[0]), "=r"(r[1]), "=r"(r[2]), "=r"(r[3]) : "r"(addr));
}
__device__ __forceinline__ void mma16816(float* c, const uint32_t* a, uint32_t b0, uint32_t b1) {
    asm volatile(
        "mma.sync.aligned.m16n8k16.row.col.f32.bf16.bf16.f32 "
        "{%0,%1,%2,%3}, {%4,%5,%6,%7}, {%8,%9}, {%0,%1,%2,%3};\n"
        : "+f"(c[0]), "+f"(c[1]), "+f"(c[2]), "+f"(c[3])
        : "r"(a[0]), "r"(a[1]), "r"(a[2]), "r"(a[3]), "r"(b0), "r"(b1));
}

// ===== prepass: streaming fp32 -> bf16, 2 float4s per thread (MLP=2) =====
#define X_F4 (BATCH * IN_DIM / 4)                         // 2,097,152 float4s
#define W1_F4 ((size_t)ATT_NUM * IN_DIM * HID / 4)        // 20,971,520 float4s
#define TOT_F4 ((size_t)X_F4 + W1_F4)                     // 23,068,672
#define CVT_THREADS (TOT_F4 / 2)                          // 11,534,336 -> grid 45056

__device__ __forceinline__ uint2 cvt_f4(float4 v) {
    __nv_bfloat162 lo = __floats2bfloat162_rn(v.x, v.y);
    __nv_bfloat162 hi = __floats2bfloat162_rn(v.z, v.w);
    uint2 u;
    u.x = *reinterpret_cast<uint32_t*>(&lo);
    u.y = *reinterpret_cast<uint32_t*>(&hi);
    return u;
}

__global__ void convert_all_kernel(const float* __restrict__ x, const float* __restrict__ W1) {
    size_t i0 = (size_t)blockIdx.x * blockDim.x + threadIdx.x;
    size_t i1 = i0 + CVT_THREADS;
    // issue both loads before converting either (MLP=2)
    float4 v0 = (i0 < X_F4) ? reinterpret_cast<const float4*>(x)[i0]
                            : reinterpret_cast<const float4*>(W1)[i0 - X_F4];
    float4 v1 = (i1 < X_F4) ? reinterpret_cast<const float4*>(x)[i1]
                            : reinterpret_cast<const float4*>(W1)[i1 - X_F4];
    uint2* d0 = (i0 < X_F4) ? reinterpret_cast<uint2*>(g_xb) + i0
                            : reinterpret_cast<uint2*>(g_w1b) + (i0 - X_F4);
    uint2* d1 = (i1 < X_F4) ? reinterpret_cast<uint2*>(g_xb) + i1
                            : reinterpret_cast<uint2*>(g_w1b) + (i1 - X_F4);
    *d0 = cvt_f4(v0);
    *d1 = cvt_f4(v1);
}

// ===== fused GEMM + bias + gelu + W2-dot =====
extern __shared__ __align__(1024) char dynsmem[];

// One quarter of a chunk's loads: A 1 cp16/thread + B 1 cp16/thread.
__device__ __forceinline__ void load_part(uint32_t smem_base, int kc, int s, int part,
                                          const __nv_bfloat16* xA, const __nv_bfloat16* wB,
                                          int tid) {
    uint32_t ab = smem_base + A_OFF(s);
    uint32_t bb = smem_base + B_OFF(s);
    const __nv_bfloat16* xk = xA + kc * KC;
    const __nv_bfloat16* wk = wB + (size_t)(kc * KC) * HID;   // [k][n], n contiguous
    int o = tid + part * 256;                                 // 0..1023
    {
        int row = o >> 3, j = o & 7;                          // A: 128 rows x 8 x 16B
        uint32_t bo = (uint32_t)((row << 7) | (j << 4));
        uint32_t sw = bo ^ ((bo >> 3) & 0x70);
        cp16(ab + sw, xk + (size_t)row * IN_DIM + j * 8);
    }
    {
        int krow = o >> 4, c = o & 15;                        // B: 64 rows x 16 x 16B
        uint32_t sw = (uint32_t)(krow * 256) + (uint32_t)((c ^ (krow & 7)) << 4);
        cp16(bb + sw, wk + (size_t)krow * HID + c * 8);
    }
}

__global__ __launch_bounds__(256, 2)
void fused_head_gemm(const float* __restrict__ b1, const float* __restrict__ W2) {
    uint32_t smem_base = smem_u32(dynsmem);
    const int tid  = threadIdx.x;
    const int wid  = tid >> 5;
    const int lane = tid & 31;
    const int warp_m = wid & 1;     // 2 warps in M (64 rows each)
    const int warp_n = wid >> 1;    // 4 warps in N (32 cols each)
    const int g = lane >> 2;
    const int t = lane & 3;

    const int m0 = blockIdx.x * BM;
    const int n0 = blockIdx.y * BN;
    const int a  = blockIdx.z;

    const __nv_bfloat16* xA = g_xb  + (size_t)m0 * IN_DIM;
    const __nv_bfloat16* wB = g_w1b + (size_t)a * IN_DIM * HID + n0;

    if (tid < BN) {   // bias / W2 tile to smem
        float* b1s = (float*)(dynsmem + OFF_B1S);
        float* w2s = (float*)(dynsmem + OFF_W2S);
        b1s[tid] = b1[a * HID + n0 + tid];
        w2s[tid] = W2[a * HID + n0 + tid];
    }

    // ---- lane constants for fragment loads ----
    const int arow = lane & 15;
    const int ahi  = lane >> 4;
    const int asw  = arow & 7;
    const int krow_l = (((lane >> 3) & 1) << 3) + (lane & 7);
    const int nc_l   = lane >> 4;
    const int bxor   = krow_l & 7;

    uint32_t a_rowbase[4];
    #pragma unroll
    for (int fm = 0; fm < 4; fm++)
        a_rowbase[fm] = (uint32_t)((warp_m * 64 + fm * 16 + arow) << 7);
    uint32_t b_coloff[2];
    #pragma unroll
    for (int p = 0; p < 2; p++)
        b_coloff[p] = (uint32_t)((((warp_n * 4 + p * 2 + nc_l) ^ bxor)) << 4);

    float acc[4][4][4];
    #pragma unroll
    for (int fm = 0; fm < 4; fm++)
        #pragma unroll
        for (int fn = 0; fn < 4; fn++)
            #pragma unroll
            for (int r = 0; r < 4; r++) acc[fm][fn][r] = 0.0f;

    // prologue: stages 0..NSTG-2
    #pragma unroll
    for (int s = 0; s < NSTG - 1; s++) {
        #pragma unroll
        for (int part = 0; part < 4; part++) load_part(smem_base, s, s, part, xA, wB, tid);
        CP_COMMIT();
    }

    uint32_t Af[4][4], Bf[2][4];   // single-buffered; cross-CTA interleave hides latency

    for (int kc = 0; kc < NC; ++kc) {
        if (kc == NC - 1) { CP_WAIT(0); } else { CP_WAIT(1); }
        __syncthreads();
        const uint32_t abase = smem_base + A_OFF(kc % NSTG);
        const uint32_t bbase = smem_base + B_OFF(kc % NSTG);
        const int pf = (kc + NSTG - 1 < NC);
        const int pfs = (kc + NSTG - 1) % NSTG;

        #pragma unroll
        for (int ks = 0; ks < 4; ks++) {
            #pragma unroll
            for (int p = 0; p < 2; p++)
                ldsm4t(Bf[p], bbase + (uint32_t)((ks * 16 + krow_l) * 256) + b_coloff[p]);
            #pragma unroll
            for (int fm = 0; fm < 4; fm++)
                ldsm4(Af[fm], abase + a_rowbase[fm] + (((ks * 2 + ahi) ^ asw) << 4));
            if (pf) load_part(smem_base, kc + NSTG - 1, pfs, ks, xA, wB, tid);
            #pragma unroll
            for (int fm = 0; fm < 4; fm++)
                #pragma unroll
                for (int p = 0; p < 2; p++) {
                    mma16816(acc[fm][2 * p],     Af[fm], Bf[p][0], Bf[p][1]);
                    mma16816(acc[fm][2 * p + 1], Af[fm], Bf[p][2], Bf[p][3]);
                }
        }
        if (pf) CP_COMMIT();
    }

    // ---- epilogue ----
    const float* b1s = (const float*)(dynsmem + OFF_B1S);
    const float* w2s = (const float*)(dynsmem + OFF_W2S);
    float* red = (float*)(dynsmem + OFF_RED);   // [128][4]

    float pr[8];
    #pragma unroll
    for (int i = 0; i < 8; i++) pr[i] = 0.0f;

    #pragma unroll
    for (int fm = 0; fm < 4; fm++) {
        #pragma unroll
        for (int fn = 0; fn < 4; fn++) {
            int cbase = warp_n * 32 + fn * 8 + 2 * t;
            #pragma unroll
            for (int cc = 0; cc < 2; cc++) {
                int col = cbase + cc;
                float bb = b1s[col];
                float w2 = w2s[col];
                float v0 = acc[fm][fn][cc]     + bb;
                float v1 = acc[fm][fn][cc + 2] + bb;
                float h0 = 0.5f * v0 * (1.0f + erff(v0 * 0.70710678118654752f));
                float h1 = 0.5f * v1 * (1.0f + erff(v1 * 0.70710678118654752f));
                pr[fm * 2 + 0] += h0 * w2;
                pr[fm * 2 + 1] += h1 * w2;
            }
        }
    }
    #pragma unroll
    for (int i = 0; i < 8; i++) {
        pr[i] += __shfl_xor_sync(0xffffffffu, pr[i], 1);
        pr[i] += __shfl_xor_sync(0xffffffffu, pr[i], 2);
    }
    __syncthreads();
    if (t == 0) {
        #pragma unroll
        for (int i = 0; i < 8; i++) {
            int row = warp_m * 64 + (i >> 1) * 16 + (i & 1) * 8 + g;
            red[row * 4 + warp_n] = pr[i];
        }
    }
    __syncthreads();
    if (tid < BM) {
        float sum = red[tid * 4 + 0] + red[tid * 4 + 1] + red[tid * 4 + 2] + red[tid * 4 + 3];
        g_ypart[((size_t)(m0 + tid) * ATT_NUM + a) * NTILES + blockIdx.y] = sum;
    }
}

__global__ void finalize_kernel(const float* __restrict__ b2, float* __restrict__ out) {
    int i = blockIdx.x * blockDim.x + threadIdx.x;
    if (i >= BATCH * ATT_NUM) return;
    int a = i % ATT_NUM;
    float s = 0.0f;
    #pragma unroll
    for (int j = 0; j < NTILES; j++) s += g_ypart[(size_t)i * NTILES + j];
    s += b2[a];
    out[i] = 1.0f / (1.0f + expf(-s));
}

extern "C" void kernel_launch(void* const* d_in, const int* in_sizes, int n_in,
                              void* d_out, int out_size) {
    const float* x  = (const float*)d_in[0];
    const float* W1 = (const float*)d_in[1];
    const float* b1 = (const float*)d_in[2];
    const float* W2 = (const float*)d_in[3];
    const float* b2 = (const float*)d_in[4];
    float* out = (float*)d_out;

    cudaFuncSetAttribute(fused_head_gemm, cudaFuncAttributeMaxDynamicSharedMemorySize, SMEM_TOTAL);

    convert_all_kernel<<<(unsigned)(CVT_THREADS / 256), 256>>>(x, W1);

    dim3 grid(BATCH / BM, HID / BN, ATT_NUM);   // (32, 8, 40); x fastest -> W1 strip reuse in-wave
    fused_head_gemm<<<grid, 256, SMEM_TOTAL>>>(b1, W2);

    int n = BATCH * ATT_NUM;
    finalize_kernel<<<(n + 255) / 256, 256>>>(b2, out);
}